// round 5
// baseline (speedup 1.0000x reference)
#include <cuda_runtime.h>

// CRF_14379550507279 fixed shapes:
//   emissions (B=512, S=2048, T=32) f32, tags (B,S) i32, mask (B,S) f32,
//   transitions (32,32) f32. Output: scalar f32.
//
// total = sum_b sum_t trans[tags[b,0],t]
//       + sum_{b,s,t} w(b,s) * em[b,s,t]       (w = 1 at s==0, else mask[b,s])
//       + 32 * sum_{b,s>=1} trans[tags[b,s-1],tags[b,s]] * mask[b,s]

#define NTAGS 32
#define B_DIM 512
#define S_DIM 2048
#define GRID 1024
#define BLOCK 256
#define STRIDE (GRID * BLOCK)          // 262144 chunks
#define ROWSTRIDE (STRIDE / 8)         // 32768 rows; multiple of S_DIM
#define TOTAL_CHUNKS (B_DIM * S_DIM * 8)
#define ITERS (TOTAL_CHUNKS / STRIDE)  // 32, exact

__device__ double g_acc = 0.0;
__device__ unsigned int g_count = 0;

__global__ void __launch_bounds__(BLOCK, 6) crf_fused_kernel(
    const float4* __restrict__ em4,    // B*S*8 float4 chunks (32 floats/row)
    const int* __restrict__ tags,      // B*S
    const float* __restrict__ mask,    // B*S
    const float* __restrict__ trans,   // 32*32
    float* __restrict__ out)
{
    __shared__ float s_trans[NTAGS * NTAGS];
    for (int i = threadIdx.x; i < NTAGS * NTAGS; i += BLOCK)
        s_trans[i] = trans[i];
    __syncthreads();

    const int q0 = blockIdx.x * BLOCK + threadIdx.x;
    const int row0 = q0 >> 3;
    // loop-invariant per thread: stride is a multiple of 8 and of 8*S_DIM
    const bool lane0 = (q0 & 7) == 0;   // this chunk owns the row's trans terms
    const int s = row0 & (S_DIM - 1);   // position in sequence, invariant
    const bool first = (s == 0);

    float acc = 0.0f;

    #pragma unroll 4
    for (int it = 0; it < ITERS; it++) {
        const int row = row0 + it * ROWSTRIDE;
        const float m = __ldg(&mask[row]);
        const float w = first ? 1.0f : m;
        const float4 v = em4[q0 + it * STRIDE];
        acc += w * ((v.x + v.y) + (v.z + v.w));

        if (lane0) {
            const int tc = __ldg(&tags[row]);
            if (first) {
                // score0: full transition row for the first tag
                float ts = 0.0f;
                #pragma unroll
                for (int t = 0; t < NTAGS; t++) ts += s_trans[tc * NTAGS + t];
                acc += ts;
            } else {
                // scalar trans broadcast over T columns -> counted NTAGS times
                const int tp = __ldg(&tags[row - 1]);
                acc += (float)NTAGS * s_trans[tp * NTAGS + tc] * m;
            }
        }
    }

    // warp tree reduce
    #pragma unroll
    for (int o = 16; o > 0; o >>= 1)
        acc += __shfl_xor_sync(0xffffffffu, acc, o);

    __shared__ float warp_sums[BLOCK / 32];
    const int wid = threadIdx.x >> 5;
    if ((threadIdx.x & 31) == 0) warp_sums[wid] = acc;
    __syncthreads();

    if (threadIdx.x == 0) {
        float b = 0.0f;
        #pragma unroll
        for (int i = 0; i < BLOCK / 32; i++) b += warp_sums[i];
        atomicAdd(&g_acc, (double)b);
        __threadfence();
        // last block finalizes: write scalar, reset accumulator for next replay
        const unsigned int ticket = atomicInc(&g_count, GRID - 1);
        if (ticket == GRID - 1) {
            out[0] = (float)atomicAdd(&g_acc, 0.0);
            g_acc = 0.0;
        }
    }
}

extern "C" void kernel_launch(void* const* d_in, const int* in_sizes, int n_in,
                              void* d_out, int out_size) {
    const float* emissions   = (const float*)d_in[0];
    const int*   tags        = (const int*)d_in[1];
    const float* mask        = (const float*)d_in[2];
    const float* transitions = (const float*)d_in[3];

    crf_fused_kernel<<<GRID, BLOCK>>>(
        (const float4*)emissions, tags, mask, transitions, (float*)d_out);
}

// round 6
// speedup vs baseline: 1.9586x; 1.9586x over previous
#include <cuda_runtime.h>

// CRF_14379550507279 fixed shapes:
//   emissions (B=512, S=2048, T=32) f32, tags (B,S) i32, mask (B,S) f32,
//   transitions (32,32) f32. Output: scalar f32.
//
// total = sum_{all b,s,t} mask[b,s]*em[b,s,t]                         (phase 2, branch-free)
//       + sum_b [ (1-mask[b,0])*sum_t em[b,0,t] + sum_t trans[tags[b,0],t] ]   (phase 1, s==0)
//       + 32 * sum_{b,s>=1} trans[tags[b,s-1],tags[b,s]] * mask[b,s]           (phase 1, s>0)

#define NTAGS 32
#define B_DIM 512
#define S_DIM 2048
#define BS_ROWS (B_DIM * S_DIM)            // 1048576
#define GRID 1024
#define BLOCK 256
#define NTHREADS (GRID * BLOCK)            // 262144
#define TOTAL_CHUNKS (BS_ROWS * 8)         // 8388608 float4 chunks
#define ITERS (TOTAL_CHUNKS / NTHREADS)    // 32, exact
#define ROWS_PER_THREAD (BS_ROWS / NTHREADS) // 4, exact

__device__ double g_acc = 0.0;
__device__ unsigned int g_count = 0;

__global__ void __launch_bounds__(BLOCK, 8) crf_fused_kernel(
    const float4* __restrict__ em4,    // B*S*8 float4 chunks (32 floats/row)
    const int* __restrict__ tags,      // B*S
    const float* __restrict__ mask,    // B*S
    const float* __restrict__ trans,   // 32*32
    float* __restrict__ out)
{
    __shared__ float s_trans[NTAGS * NTAGS];
    for (int i = threadIdx.x; i < NTAGS * NTAGS; i += BLOCK)
        s_trans[i] = trans[i];
    __syncthreads();

    const int tid = blockIdx.x * BLOCK + threadIdx.x;
    float acc = 0.0f;

    // ---- Phase 1: transition terms + s==0 correction (4 rows/thread, striped).
    // NTHREADS is a multiple of S_DIM, so s = row & (S_DIM-1) = tid & (S_DIM-1)
    // is invariant across the k-loop: the s==0 branch is per-thread uniform.
    {
        const int s = tid & (S_DIM - 1);
        if (s == 0) {
            // 128 threads total take this path (1 per 2048)
            for (int k = 0; k < ROWS_PER_THREAD; k++) {
                const int row = tid + k * NTHREADS;
                const int tc = tags[row];
                const float m = mask[row];
                float ts = 0.0f;
                #pragma unroll
                for (int t = 0; t < NTAGS; t++) ts += s_trans[tc * NTAGS + t];
                // phase 2 will weight this row by mask[b,0]; reference wants weight 1
                float es = 0.0f;
                const float4* p = em4 + (long)row * 8;
                for (int i = 0; i < 8; i++) {
                    const float4 v = p[i];
                    es += (v.x + v.y) + (v.z + v.w);
                }
                acc += ts + (1.0f - m) * es;
            }
        } else {
            #pragma unroll
            for (int k = 0; k < ROWS_PER_THREAD; k++) {
                const int row = tid + k * NTHREADS;
                const int tc = tags[row];
                const int tp = tags[row - 1];
                const float m = mask[row];
                // scalar trans broadcast over T columns -> counted NTAGS times
                acc += (float)NTAGS * s_trans[tp * NTAGS + tc] * m;
            }
        }
    }

    // ---- Phase 2: branch-free masked emission streaming (32 iters/thread, exact).
    #pragma unroll 4
    for (int it = 0; it < ITERS; it++) {
        const int q = tid + it * NTHREADS;
        const float4 v = __ldcs(em4 + q);          // streaming: no reuse
        const float m = mask[q >> 3];              // L2-resident, x8 reuse
        acc += m * ((v.x + v.y) + (v.z + v.w));
    }

    // ---- Reduce: warp tree -> block -> global double atomic.
    #pragma unroll
    for (int o = 16; o > 0; o >>= 1)
        acc += __shfl_xor_sync(0xffffffffu, acc, o);

    __shared__ float warp_sums[BLOCK / 32];
    const int wid = threadIdx.x >> 5;
    if ((threadIdx.x & 31) == 0) warp_sums[wid] = acc;
    __syncthreads();

    if (threadIdx.x == 0) {
        float b = 0.0f;
        #pragma unroll
        for (int i = 0; i < BLOCK / 32; i++) b += warp_sums[i];
        atomicAdd(&g_acc, (double)b);
        __threadfence();
        // last block finalizes: write scalar, reset accumulator for next replay
        const unsigned int ticket = atomicInc(&g_count, GRID - 1);
        if (ticket == GRID - 1) {
            out[0] = (float)atomicAdd(&g_acc, 0.0);
            g_acc = 0.0;
        }
    }
}

extern "C" void kernel_launch(void* const* d_in, const int* in_sizes, int n_in,
                              void* d_out, int out_size) {
    const float* emissions   = (const float*)d_in[0];
    const int*   tags        = (const int*)d_in[1];
    const float* mask        = (const float*)d_in[2];
    const float* transitions = (const float*)d_in[3];

    crf_fused_kernel<<<GRID, BLOCK>>>(
        (const float4*)emissions, tags, mask, transitions, (float*)d_out);
}

// round 7
// speedup vs baseline: 2.1776x; 1.1118x over previous
#include <cuda_runtime.h>

// CRF_14379550507279 fixed shapes:
//   emissions (B=512, S=2048, T=32) f32, tags (B,S) i32, mask (B,S) f32,
//   transitions (32,32) f32. Output: scalar f32.
//
// total = sum_{all b,s,t} mask[b,s]*em[b,s,t]                              (phase 2)
//       + sum_b [ (1-mask[b,0])*sum_t em[b,0,t] + sum_t trans[tags[b,0],t] ] (phase 1b)
//       + 32 * sum_{b,s>=1} trans[tags[b,s-1],tags[b,s]] * mask[b,s]        (phase 1a)

#define NTAGS 32
#define B_DIM 512
#define S_DIM 2048
#define BS_ROWS (B_DIM * S_DIM)             // 1048576
#define GRID 1184                           // 148 SMs * 8 CTAs: one even wave
#define BLOCK 128
#define NT (GRID * BLOCK)                   // 151552 threads
#define NTR (NT / 8)                        // mask/row stride per body step
#define TOTAL_CHUNKS (BS_ROWS * 8)          // 8388608 float4 chunks

__device__ double g_acc = 0.0;
__device__ unsigned int g_count = 0;

__device__ __forceinline__ float hsum4(float4 v) {
    return (v.x + v.y) + (v.z + v.w);
}

__global__ void __launch_bounds__(BLOCK, 8) crf_fused_kernel(
    const float4* __restrict__ em4,    // B*S*8 float4 chunks (32 floats/row)
    const int* __restrict__ tags,      // B*S
    const float* __restrict__ mask,    // B*S
    const float* __restrict__ trans,   // 32*32
    float* __restrict__ out)
{
    __shared__ float s_trans[NTAGS * NTAGS];
    for (int i = threadIdx.x; i < NTAGS * NTAGS; i += BLOCK)
        s_trans[i] = trans[i];
    __syncthreads();

    const int tid = blockIdx.x * BLOCK + threadIdx.x;
    float acc = 0.0f;

    // ---- Phase 1a: transition steps, fully branch-free (predicated).
    // For s==0 rows w=0 kills the bogus term; tags[max(row-1,0)] stays in-bounds.
    for (int row = tid; row < BS_ROWS; row += NT) {
        const int s = row & (S_DIM - 1);
        const int tc = tags[row];
        const int tp = tags[(row > 0) ? (row - 1) : 0];
        const float w = (s == 0) ? 0.0f : __ldg(&mask[row]);
        acc += (float)NTAGS * s_trans[tp * NTAGS + tc] * w;
    }

    // ---- Phase 1b: s==0 specials, 512 terms, one thread per batch.
    if (tid < B_DIM) {
        const int row = tid * S_DIM;
        const int tc = tags[row];
        const float m = mask[row];
        float ts = 0.0f;
        #pragma unroll
        for (int t = 0; t < NTAGS; t++) ts += s_trans[tc * NTAGS + t];
        float es = 0.0f;
        const float4* p = em4 + (long)row * 8;
        #pragma unroll
        for (int i = 0; i < 8; i++) es += hsum4(p[i]);
        // phase 2 weights this row by mask[b,0]; reference wants weight 1
        acc += ts + (1.0f - m) * es;
    }

    // ---- Phase 2: branch-free masked emission stream, 8-deep load batches.
    float a0 = 0.0f, a1 = 0.0f, a2 = 0.0f, a3 = 0.0f;
    int q = tid;
    const int mrow0 = tid >> 3;
    int mr = mrow0;
    for (; q + 7 * NT < TOTAL_CHUNKS; q += 8 * NT, mr += 8 * NTR) {
        // front-batch 8 independent LDG.128 + 8 mask LDG.32
        const float4 v0 = __ldcs(em4 + q + 0 * NT);
        const float4 v1 = __ldcs(em4 + q + 1 * NT);
        const float4 v2 = __ldcs(em4 + q + 2 * NT);
        const float4 v3 = __ldcs(em4 + q + 3 * NT);
        const float4 v4 = __ldcs(em4 + q + 4 * NT);
        const float4 v5 = __ldcs(em4 + q + 5 * NT);
        const float4 v6 = __ldcs(em4 + q + 6 * NT);
        const float4 v7 = __ldcs(em4 + q + 7 * NT);
        const float m0 = __ldg(&mask[mr + 0 * NTR]);
        const float m1 = __ldg(&mask[mr + 1 * NTR]);
        const float m2 = __ldg(&mask[mr + 2 * NTR]);
        const float m3 = __ldg(&mask[mr + 3 * NTR]);
        const float m4 = __ldg(&mask[mr + 4 * NTR]);
        const float m5 = __ldg(&mask[mr + 5 * NTR]);
        const float m6 = __ldg(&mask[mr + 6 * NTR]);
        const float m7 = __ldg(&mask[mr + 7 * NTR]);
        a0 += m0 * hsum4(v0);
        a1 += m1 * hsum4(v1);
        a2 += m2 * hsum4(v2);
        a3 += m3 * hsum4(v3);
        a0 += m4 * hsum4(v4);
        a1 += m5 * hsum4(v5);
        a2 += m6 * hsum4(v6);
        a3 += m7 * hsum4(v7);
    }
    // tail (<= 7 iterations per thread)
    for (; q < TOTAL_CHUNKS; q += NT, mr += NTR) {
        const float4 v = __ldcs(em4 + q);
        a0 += __ldg(&mask[mr]) * hsum4(v);
    }
    acc += (a0 + a1) + (a2 + a3);

    // ---- Reduce: warp tree -> block -> global double atomic.
    #pragma unroll
    for (int o = 16; o > 0; o >>= 1)
        acc += __shfl_xor_sync(0xffffffffu, acc, o);

    __shared__ float warp_sums[BLOCK / 32];
    const int wid = threadIdx.x >> 5;
    if ((threadIdx.x & 31) == 0) warp_sums[wid] = acc;
    __syncthreads();

    if (threadIdx.x == 0) {
        float b = 0.0f;
        #pragma unroll
        for (int i = 0; i < BLOCK / 32; i++) b += warp_sums[i];
        atomicAdd(&g_acc, (double)b);
        __threadfence();
        // last block finalizes: write scalar, reset accumulator for next replay
        const unsigned int ticket = atomicInc(&g_count, GRID - 1);
        if (ticket == GRID - 1) {
            out[0] = (float)atomicAdd(&g_acc, 0.0);
            g_acc = 0.0;
        }
    }
}

extern "C" void kernel_launch(void* const* d_in, const int* in_sizes, int n_in,
                              void* d_out, int out_size) {
    const float* emissions   = (const float*)d_in[0];
    const int*   tags        = (const int*)d_in[1];
    const float* mask        = (const float*)d_in[2];
    const float* transitions = (const float*)d_in[3];

    crf_fused_kernel<<<GRID, BLOCK>>>(
        (const float4*)emissions, tags, mask, transitions, (float*)d_out);
}